// round 1
// baseline (speedup 1.0000x reference)
#include <cuda_runtime.h>
#include <cuda_bf16.h>

#define TH 512
#define MT 64
#define PITCH 68   // MT + 4, conflict-free strides

// ---------------- device globals (no allocs allowed) ----------------
__device__ float g_scores[8 * 4096];
__device__ float g_probs[8 * 4096];

// ---------------- f32x2 helpers (sm_103a packed fp32 FMA) ----------------
__device__ __forceinline__ unsigned long long pk2(float a, float b) {
    unsigned long long r;
    asm("mov.b64 %0, {%1,%2};" : "=l"(r) : "f"(a), "f"(b));
    return r;
}
__device__ __forceinline__ void upk2(unsigned long long v, float& a, float& b) {
    asm("mov.b64 {%0,%1}, %2;" : "=f"(a), "=f"(b) : "l"(v));
}
__device__ __forceinline__ unsigned long long fma2(unsigned long long a,
                                                   unsigned long long b,
                                                   unsigned long long c) {
    unsigned long long d;
    asm("fma.rn.f32x2 %0, %1, %2, %3;" : "=l"(d) : "l"(a), "l"(b), "l"(c));
    return d;
}

// ---------------- row-wise instance norm over 256 dims ----------------
// X layout: X[k*PITCH + r], k in [0,256), r in [0,64)
__device__ __forceinline__ void rownorm(float* X, float* red1, float* red2,
                                        float* rowM, float* rowR, int tid) {
    int r = tid & 63, part = tid >> 6;  // 8 parts x 64 rows
    float s1 = 0.f, s2 = 0.f;
    const float* base = X + (part * 32) * PITCH + r;
#pragma unroll
    for (int g = 0; g < 32; g++) {
        float v = base[g * PITCH];
        s1 += v;
        s2 += v * v;
    }
    red1[part * 64 + r] = s1;
    red2[part * 64 + r] = s2;
    __syncthreads();
    if (tid < 64) {
        float a = 0.f, bq = 0.f;
#pragma unroll
        for (int p = 0; p < 8; p++) {
            a += red1[p * 64 + tid];
            bq += red2[p * 64 + tid];
        }
        float m = a * (1.f / 256.f);
        float var = bq * (1.f / 256.f) - m * m;
        rowM[tid] = m;
        rowR[tid] = rsqrtf(var + 1e-5f);
    }
    __syncthreads();
    for (int idx = tid; idx < 256 * 64; idx += TH) {
        int c = idx >> 6, rr = idx & 63;
        float* p = X + c * PITCH + rr;
        *p = (*p - rowM[rr]) * rowR[rr];
    }
    __syncthreads();
}

// ---------------- tiled GEMM: Y[r][c] = act( sum_k X[k][r]*W[k][c] + b[c] ) ----------------
// src col-major (PITCH), dst col-major (PITCH). act: 0=relu, 1=leaky(0.01)
__device__ __forceinline__ void mlp_gemm(const float* __restrict__ src,
                                         float* __restrict__ dst,
                                         const float* __restrict__ Wg,
                                         const float* __restrict__ bias,
                                         float* WT, int Krows, int Ktiles,
                                         int act, int tid) {
    int tr = tid >> 5;  // 0..15 -> rows 4*tr..4*tr+3
    int tc = tid & 31;  // col pairs 2*tc + 64*jp
    unsigned long long acc[4][4];
#pragma unroll
    for (int i = 0; i < 4; i++)
#pragma unroll
        for (int jp = 0; jp < 4; jp++) acc[i][jp] = 0ull;

    const float4* W4 = (const float4*)Wg;
    float4* WT4 = (float4*)WT;

    for (int kt = 0; kt < Ktiles; kt++) {
        // cooperative load of W tile [32][256]
#pragma unroll
        for (int i = 0; i < 4; i++) {
            int f4i = tid + TH * i;
            int row = (f4i >> 6) + kt * 32;
            float4 v = make_float4(0.f, 0.f, 0.f, 0.f);
            if (row < Krows) v = W4[row * 64 + (f4i & 63)];
            WT4[f4i] = v;
        }
        __syncthreads();
#pragma unroll 8
        for (int k = 0; k < 32; k++) {
            const float4 xv = *(const float4*)(src + (kt * 32 + k) * PITCH + 4 * tr);
            unsigned long long xr0 = pk2(xv.x, xv.x);
            unsigned long long xr1 = pk2(xv.y, xv.y);
            unsigned long long xr2 = pk2(xv.z, xv.z);
            unsigned long long xr3 = pk2(xv.w, xv.w);
#pragma unroll
            for (int jp = 0; jp < 4; jp++) {
                unsigned long long w2 =
                    *(const unsigned long long*)(WT + k * 256 + 2 * tc + 64 * jp);
                acc[0][jp] = fma2(xr0, w2, acc[0][jp]);
                acc[1][jp] = fma2(xr1, w2, acc[1][jp]);
                acc[2][jp] = fma2(xr2, w2, acc[2][jp]);
                acc[3][jp] = fma2(xr3, w2, acc[3][jp]);
            }
        }
        __syncthreads();
    }
    // epilogue: bias + activation + store (float4 along rows)
#pragma unroll
    for (int jp = 0; jp < 4; jp++) {
        int c0 = 2 * tc + 64 * jp;
        float b0 = bias[c0], b1 = bias[c0 + 1];
        float y0[4], y1[4];
#pragma unroll
        for (int i = 0; i < 4; i++) {
            float lo, hi;
            upk2(acc[i][jp], lo, hi);
            lo += b0;
            hi += b1;
            if (act == 0) {
                lo = fmaxf(lo, 0.f);
                hi = fmaxf(hi, 0.f);
            } else {
                lo = (lo > 0.f) ? lo : 0.01f * lo;
                hi = (hi > 0.f) ? hi : 0.01f * hi;
            }
            y0[i] = lo;
            y1[i] = hi;
        }
        *(float4*)(dst + c0 * PITCH + 4 * tr) = make_float4(y0[0], y0[1], y0[2], y0[3]);
        *(float4*)(dst + (c0 + 1) * PITCH + 4 * tr) = make_float4(y1[0], y1[1], y1[2], y1[3]);
    }
    __syncthreads();
}

// ---------------- main fused kernel: one CTA = 64 subset rows of one batch ----------------
__global__ void __launch_bounds__(TH, 1)
fused_main(const float* __restrict__ vf, const float* __restrict__ vmask,
           const float* __restrict__ eoh_g, const int* __restrict__ subs,
           const float* __restrict__ cW, const float* __restrict__ cB,
           const float* __restrict__ w1, const float* __restrict__ b1,
           const float* __restrict__ w2a, const float* __restrict__ b2a,
           const float* __restrict__ w2b, const float* __restrict__ b2b,
           const float* __restrict__ sW, const float* __restrict__ sB) {
    extern __shared__ float sm[];
    float* XA = sm;                 // 384*68 = 26112 floats
    float* XB = sm + 26112;         // 256*68 = 17408
    float* WT = sm + 43520;         // 32*256 = 8192
    float* red1 = sm + 51712;       // 512
    float* red2 = sm + 52224;       // 512
    float* rowM = sm + 52736;       // 64
    float* rowR = sm + 52800;       // 64
    float* invs = sm + 52864;       // 64
    float* maskv = sm + 52928;      // 48
    float* eoh = sm + 52976;        // 240  -> total 53216 floats

    int tid = threadIdx.x;
    int b = blockIdx.x >> 6;          // 64 tiles per batch
    int s0 = (blockIdx.x & 63) * MT;

    float* MV = XB;   // alias: masked vert feat [48][256]
    float* SUB = WT;  // alias: subset tile [64][48]

    // ---- stage B loads ----
    for (int idx = tid; idx < 48 * 256; idx += TH) {
        int a = idx >> 8;
        float m = vmask[b * 48 + a];
        MV[idx] = vf[(b * 48 + a) * 256 + (idx & 255)] * m * m;  // vf*m (masked_vert) * m (subsets_masked)
    }
    for (int idx = tid; idx < MT * 48; idx += TH) {
        int r = idx / 48, a = idx - r * 48;
        SUB[idx] = (float)subs[(b * 4096 + s0 + r) * 48 + a];
    }
    if (tid < 48) maskv[tid] = vmask[b * 48 + tid];
    if (tid < 240) eoh[tid] = eoh_g[b * 240 + tid];
    __syncthreads();

    // ---- subset-weighted sums: each thread owns one g column, 32 rows ----
    int g = tid & 255, half = tid >> 8;
    int r0 = half * 32;
    float accv[32];
#pragma unroll
    for (int i = 0; i < 32; i++) accv[i] = 0.f;
    for (int a = 0; a < 48; a++) {
        float mva = MV[a * 256 + g];
        const float* sr = SUB + r0 * 48 + a;
#pragma unroll
        for (int i = 0; i < 32; i++) accv[i] += mva * sr[i * 48];
    }
    // ---- per-row size / element counts / thermometer one-hot / zero pad ----
    if (tid < MT) {
        int r = tid;
        float sz = 0.f;
        float c0 = 0.f, c1 = 0.f, c2 = 0.f, c3 = 0.f, c4 = 0.f;
        for (int a = 0; a < 48; a++) {
            float s = SUB[r * 48 + a];
            sz += s * maskv[a];
            c0 += s * eoh[a * 5 + 0];
            c1 += s * eoh[a * 5 + 1];
            c2 += s * eoh[a * 5 + 2];
            c3 += s * eoh[a * 5 + 3];
            c4 += s * eoh[a * 5 + 4];
        }
        invs[r] = 1.f / (sz + 1e-4f);
        float cnt[5] = {c0, c1, c2, c3, c4};
#pragma unroll
        for (int e = 0; e < 5; e++)
            for (int j = 0; j < 20; j++)
                XA[(e * 20 + j) * PITCH + r] = ((float)j < cnt[e]) ? 1.f : 0.f;
        for (int j = 356; j < 384; j++) XA[j * PITCH + r] = 0.f;  // K padding
    }
    __syncthreads();
    // ---- mean feat into XA rows 100..355 ----
    {
        float* dstc = XA + (100 + g) * PITCH;
#pragma unroll
        for (int i = 0; i < 32; i++) dstc[r0 + i] = accv[i] * invs[r0 + i];
    }
    __syncthreads();

    rownorm(XA + 100 * PITCH, red1, red2, rowM, rowR, tid);           // subset_weighted_norm
    mlp_gemm(XA, XB, cW, cB, WT, 356, 12, 0, tid);                    // combine + relu
    rownorm(XB, red1, red2, rowM, rowR, tid);                         // norm_post_combine
    mlp_gemm(XB, XA, w1, b1, WT, 256, 8, 0, tid);                     // l1 + relu
    mlp_gemm(XA, XB, w2a, b2a, WT, 256, 8, 1, tid);                   // l2a + leaky
    mlp_gemm(XB, XA, w2b, b2b, WT, 256, 8, 0, tid);                   // l2b: leaky then relu == relu
    rownorm(XA, red1, red2, rowM, rowR, tid);                         // norm_pre_score

    // ---- score head ----
    {
        int r = tid & 63, part = tid >> 6;
        float s = 0.f;
#pragma unroll
        for (int gg = 0; gg < 32; gg++)
            s += XA[(part * 32 + gg) * PITCH + r] * sW[part * 32 + gg];
        red1[part * 64 + r] = s;
        __syncthreads();
        if (tid < 64) {
            float t = 0.f;
#pragma unroll
            for (int p = 0; p < 8; p++) t += red1[p * 64 + tid];
            g_scores[b * 4096 + s0 + tid] = t + sB[0];
        }
    }
}

// ---------------- per-batch softmax over 4096 scores ----------------
__global__ void softmax_kernel(float* __restrict__ probs_out) {
    __shared__ float sbuf[32];
    __shared__ float sval;
    int b = blockIdx.x, t = threadIdx.x, lane = t & 31, wid = t >> 5;
    const float* sc = g_scores + b * 4096;
    float v0 = sc[t], v1 = sc[t + 1024], v2 = sc[t + 2048], v3 = sc[t + 3072];
    float mx = fmaxf(fmaxf(v0, v1), fmaxf(v2, v3));
#pragma unroll
    for (int o = 16; o; o >>= 1) mx = fmaxf(mx, __shfl_xor_sync(0xffffffffu, mx, o));
    if (lane == 0) sbuf[wid] = mx;
    __syncthreads();
    if (t < 32) {
        float m = sbuf[t];
#pragma unroll
        for (int o = 16; o; o >>= 1) m = fmaxf(m, __shfl_xor_sync(0xffffffffu, m, o));
        if (t == 0) sval = m;
    }
    __syncthreads();
    mx = sval;
    float e0 = expf(v0 - mx), e1 = expf(v1 - mx), e2 = expf(v2 - mx), e3 = expf(v3 - mx);
    float sum = e0 + e1 + e2 + e3;
#pragma unroll
    for (int o = 16; o; o >>= 1) sum += __shfl_xor_sync(0xffffffffu, sum, o);
    __syncthreads();
    if (lane == 0) sbuf[wid] = sum;
    __syncthreads();
    if (t < 32) {
        float s = sbuf[t];
#pragma unroll
        for (int o = 16; o; o >>= 1) s += __shfl_xor_sync(0xffffffffu, s, o);
        if (t == 0) sval = s;
    }
    __syncthreads();
    float inv = 1.f / sval;
    float p0 = e0 * inv, p1 = e1 * inv, p2 = e2 * inv, p3 = e3 * inv;
    probs_out[b * 4096 + t] = p0;
    probs_out[b * 4096 + t + 1024] = p1;
    probs_out[b * 4096 + t + 2048] = p2;
    probs_out[b * 4096 + t + 3072] = p3;
    g_probs[b * 4096 + t] = p0;
    g_probs[b * 4096 + t + 1024] = p1;
    g_probs[b * 4096 + t + 2048] = p2;
    g_probs[b * 4096 + t + 3072] = p3;
}

// ---------------- zero + scatter into spectral bins ----------------
__global__ void zero_kernel(float* __restrict__ p, int n) {
    int idx = blockIdx.x * blockDim.x + threadIdx.x;
    if (idx < n) p[idx] = 0.f;
}

__global__ void scatter_kernel(const int* __restrict__ midx,
                               const float* __restrict__ inten,
                               float* __restrict__ spect) {
    int idx = blockIdx.x * blockDim.x + threadIdx.x;
    if (idx >= 8 * 4096 * 32) return;
    int b = idx >> 17;              // 4096*32 = 131072
    int s = (idx >> 5) & 4095;
    float w = inten[idx] * g_probs[b * 4096 + s];
    atomicAdd(spect + b * 65536 + midx[idx], w);
}

// ---------------- launch ----------------
extern "C" void kernel_launch(void* const* d_in, const int* in_sizes, int n_in,
                              void* d_out, int out_size) {
    const float* vf    = (const float*)d_in[0];
    const float* vmask = (const float*)d_in[1];
    const float* eoh   = (const float*)d_in[2];
    const int*   subs  = (const int*)d_in[4];
    const int*   midx  = (const int*)d_in[6];
    const float* inten = (const float*)d_in[7];
    const float* cW    = (const float*)d_in[8];
    const float* cB    = (const float*)d_in[9];
    const float* w1    = (const float*)d_in[10];
    const float* b1    = (const float*)d_in[11];
    const float* w2a   = (const float*)d_in[12];
    const float* b2a   = (const float*)d_in[13];
    const float* w2b   = (const float*)d_in[14];
    const float* b2b   = (const float*)d_in[15];
    const float* sW    = (const float*)d_in[16];
    const float* sB    = (const float*)d_in[17];
    float* out = (float*)d_out;

    int pOff = out_size - 8 * 4096;  // spect first, probs second
    size_t smem = (size_t)53216 * sizeof(float);
    cudaFuncSetAttribute(fused_main, cudaFuncAttributeMaxDynamicSharedMemorySize,
                         (int)smem);

    zero_kernel<<<(pOff + 511) / 512, 512>>>(out, pOff);
    fused_main<<<512, TH, smem>>>(vf, vmask, eoh, subs, cW, cB, w1, b1, w2a, b2a,
                                  w2b, b2b, sW, sB);
    softmax_kernel<<<8, 1024>>>(out + pOff);
    scatter_kernel<<<2048, 512>>>(midx, inten, out);
}

// round 2
// speedup vs baseline: 1.1275x; 1.1275x over previous
#include <cuda_runtime.h>
#include <cuda_bf16.h>

#define TH 512
#define MT 64
#define PITCH 68   // MT + 4, conflict-free strides

// ---------------- device globals (no allocs allowed) ----------------
__device__ float g_scores[8 * 4096];
__device__ float g_probs[8 * 4096];

// ---------------- f32x2 helpers (sm_103a packed fp32 FMA) ----------------
__device__ __forceinline__ unsigned long long pk2(float a, float b) {
    unsigned long long r;
    asm("mov.b64 %0, {%1,%2};" : "=l"(r) : "f"(a), "f"(b));
    return r;
}
__device__ __forceinline__ void upk2(unsigned long long v, float& a, float& b) {
    asm("mov.b64 {%0,%1}, %2;" : "=f"(a), "=f"(b) : "l"(v));
}
__device__ __forceinline__ unsigned long long fma2(unsigned long long a,
                                                   unsigned long long b,
                                                   unsigned long long c) {
    unsigned long long d;
    asm("fma.rn.f32x2 %0, %1, %2, %3;" : "=l"(d) : "l"(a), "l"(b), "l"(c));
    return d;
}

// ---------------- row-wise instance norm over 256 dims ----------------
// X layout: X[k*PITCH + r], k in [0,256), r in [0,64)
__device__ __forceinline__ void rownorm(float* X, float* red1, float* red2,
                                        float* rowM, float* rowR, int tid) {
    int r = tid & 63, part = tid >> 6;  // 8 parts x 64 rows
    float s1 = 0.f, s2 = 0.f;
    const float* base = X + (part * 32) * PITCH + r;
#pragma unroll
    for (int g = 0; g < 32; g++) {
        float v = base[g * PITCH];
        s1 += v;
        s2 += v * v;
    }
    red1[part * 64 + r] = s1;
    red2[part * 64 + r] = s2;
    __syncthreads();
    if (tid < 64) {
        float a = 0.f, bq = 0.f;
#pragma unroll
        for (int p = 0; p < 8; p++) {
            a += red1[p * 64 + tid];
            bq += red2[p * 64 + tid];
        }
        float m = a * (1.f / 256.f);
        float var = bq * (1.f / 256.f) - m * m;
        rowM[tid] = m;
        rowR[tid] = rsqrtf(var + 1e-5f);
    }
    __syncthreads();
    for (int idx = tid; idx < 256 * 64; idx += TH) {
        int c = idx >> 6, rr = idx & 63;
        float* p = X + c * PITCH + rr;
        *p = (*p - rowM[rr]) * rowR[rr];
    }
    __syncthreads();
}

// ---------------- tiled GEMM: Y[r][c] = act( sum_k X[k][r]*W[k][c] + b[c] ) ----------------
// src/dst col-major (PITCH). Double-buffered 16-row W tiles.
// Thread map: tr = tid>>6 (rows 8*tr..8*tr+7), tc = tid&63 (cols tc+64c).
// acc packed along ROW pairs -> X loads are natural LDS.128 reg-pairs (0 MOV),
// W is scalar LDS.32 + 1 MOV dup. Halves smem crossbar traffic vs col-pairs.
__device__ __forceinline__ void mlp_gemm(const float* __restrict__ src,
                                         float* __restrict__ dst,
                                         const float* __restrict__ Wg,
                                         const float* __restrict__ bias,
                                         float* W0, float* W1, int Krows,
                                         int Ktiles, int act, int tid) {
    int tr = tid >> 6;  // 0..7
    int tc = tid & 63;
    unsigned long long acc[4][4];
#pragma unroll
    for (int i = 0; i < 4; i++)
#pragma unroll
        for (int c = 0; c < 4; c++) acc[i][c] = 0ull;

    const float4* W4 = (const float4*)Wg;
    float4 stg[2];

    // prologue: tile0 -> W0, prefetch tile1 to regs
#pragma unroll
    for (int i = 0; i < 2; i++) {
        int f4i = tid + TH * i;
        int row = (f4i >> 6);
        stg[i] = make_float4(0.f, 0.f, 0.f, 0.f);
        if (row < Krows) stg[i] = W4[row * 64 + (f4i & 63)];
    }
#pragma unroll
    for (int i = 0; i < 2; i++) ((float4*)W0)[tid + TH * i] = stg[i];
    if (Ktiles > 1) {
#pragma unroll
        for (int i = 0; i < 2; i++) {
            int f4i = tid + TH * i;
            int row = (f4i >> 6) + 16;
            stg[i] = make_float4(0.f, 0.f, 0.f, 0.f);
            if (row < Krows) stg[i] = W4[row * 64 + (f4i & 63)];
        }
    }
    __syncthreads();

    for (int kt = 0; kt < Ktiles; kt++) {
        float* cur = (kt & 1) ? W1 : W0;
        float* nxt = (kt & 1) ? W0 : W1;
        if (kt + 1 < Ktiles) {
            // stage tile kt+1 into the other buffer
#pragma unroll
            for (int i = 0; i < 2; i++) ((float4*)nxt)[tid + TH * i] = stg[i];
            if (kt + 2 < Ktiles) {
#pragma unroll
                for (int i = 0; i < 2; i++) {
                    int f4i = tid + TH * i;
                    int row = (f4i >> 6) + (kt + 2) * 16;
                    stg[i] = make_float4(0.f, 0.f, 0.f, 0.f);
                    if (row < Krows) stg[i] = W4[row * 64 + (f4i & 63)];
                }
            }
        }
        const float* xbase = src + (kt * 16) * PITCH + 8 * tr;
#pragma unroll
        for (int k = 0; k < 16; k++) {
            float4 xa = *(const float4*)(xbase + k * PITCH);
            float4 xb = *(const float4*)(xbase + k * PITCH + 4);
            unsigned long long xp0 = pk2(xa.x, xa.y);
            unsigned long long xp1 = pk2(xa.z, xa.w);
            unsigned long long xp2 = pk2(xb.x, xb.y);
            unsigned long long xp3 = pk2(xb.z, xb.w);
            const float* wr = cur + k * 256 + tc;
#pragma unroll
            for (int c = 0; c < 4; c++) {
                float w = wr[64 * c];
                unsigned long long wd = pk2(w, w);
                acc[0][c] = fma2(xp0, wd, acc[0][c]);
                acc[1][c] = fma2(xp1, wd, acc[1][c]);
                acc[2][c] = fma2(xp2, wd, acc[2][c]);
                acc[3][c] = fma2(xp3, wd, acc[3][c]);
            }
        }
        __syncthreads();
    }

    // epilogue: bias + activation + store (rows contiguous -> float4)
#pragma unroll
    for (int c = 0; c < 4; c++) {
        int col = tc + 64 * c;
        float bb = __ldg(bias + col);
        float y[8];
#pragma unroll
        for (int rp = 0; rp < 4; rp++) {
            float lo, hi;
            upk2(acc[rp][c], lo, hi);
            lo += bb;
            hi += bb;
            if (act == 0) {
                lo = fmaxf(lo, 0.f);
                hi = fmaxf(hi, 0.f);
            } else {
                lo = (lo > 0.f) ? lo : 0.01f * lo;
                hi = (hi > 0.f) ? hi : 0.01f * hi;
            }
            y[2 * rp] = lo;
            y[2 * rp + 1] = hi;
        }
        float* dcol = dst + col * PITCH + 8 * tr;
        *(float4*)dcol = make_float4(y[0], y[1], y[2], y[3]);
        *(float4*)(dcol + 4) = make_float4(y[4], y[5], y[6], y[7]);
    }
    __syncthreads();
}

// ---------------- main fused kernel: one CTA = 64 subset rows of one batch ----------------
__global__ void __launch_bounds__(TH, 1)
fused_main(const float* __restrict__ vf, const float* __restrict__ vmask,
           const float* __restrict__ eoh_g, const int* __restrict__ subs,
           const float* __restrict__ cW, const float* __restrict__ cB,
           const float* __restrict__ w1, const float* __restrict__ b1,
           const float* __restrict__ w2a, const float* __restrict__ b2a,
           const float* __restrict__ w2b, const float* __restrict__ b2b,
           const float* __restrict__ sW, const float* __restrict__ sB) {
    extern __shared__ float sm[];
    float* XA = sm;                 // 384*68 = 26112 floats
    float* XB = sm + 26112;         // 256*68 = 17408
    float* W0 = sm + 43520;         // 16*256 = 4096
    float* W1 = sm + 47616;         // 16*256 = 4096
    float* red1 = sm + 51712;       // 512
    float* red2 = sm + 52224;       // 512
    float* rowM = sm + 52736;       // 64
    float* rowR = sm + 52800;       // 64
    float* invs = sm + 52864;       // 64
    float* maskv = sm + 52928;      // 48
    float* eoh = sm + 52976;        // 240  -> total 53216 floats

    int tid = threadIdx.x;
    int b = blockIdx.x >> 6;          // 64 tiles per batch
    int s0 = (blockIdx.x & 63) * MT;

    float* MV = XB;   // alias: masked vert feat [48][256]
    float* SUB = W0;  // alias: subset tile [64][48] (3072 <= 8192 of W0+W1)

    // ---- stage B loads ----
    for (int idx = tid; idx < 48 * 256; idx += TH) {
        int a = idx >> 8;
        float m = vmask[b * 48 + a];
        MV[idx] = vf[(b * 48 + a) * 256 + (idx & 255)] * m * m;  // vf*m * m
    }
    for (int idx = tid; idx < MT * 48; idx += TH) {
        int r = idx / 48, a = idx - r * 48;
        SUB[idx] = (float)subs[(b * 4096 + s0 + r) * 48 + a];
    }
    if (tid < 48) maskv[tid] = vmask[b * 48 + tid];
    if (tid < 240) eoh[tid] = eoh_g[b * 240 + tid];
    __syncthreads();

    // ---- subset-weighted sums: each thread owns one g column, 32 rows ----
    int g = tid & 255, half = tid >> 8;
    int r0 = half * 32;
    float accv[32];
#pragma unroll
    for (int i = 0; i < 32; i++) accv[i] = 0.f;
    for (int a = 0; a < 48; a++) {
        float mva = MV[a * 256 + g];
        const float* sr = SUB + r0 * 48 + a;
#pragma unroll
        for (int i = 0; i < 32; i++) accv[i] += mva * sr[i * 48];
    }
    // ---- per-row size / element counts / thermometer one-hot / zero pad ----
    if (tid < MT) {
        int r = tid;
        float sz = 0.f;
        float c0 = 0.f, c1 = 0.f, c2 = 0.f, c3 = 0.f, c4 = 0.f;
        for (int a = 0; a < 48; a++) {
            float s = SUB[r * 48 + a];
            sz += s * maskv[a];
            c0 += s * eoh[a * 5 + 0];
            c1 += s * eoh[a * 5 + 1];
            c2 += s * eoh[a * 5 + 2];
            c3 += s * eoh[a * 5 + 3];
            c4 += s * eoh[a * 5 + 4];
        }
        invs[r] = 1.f / (sz + 1e-4f);
        float cnt[5] = {c0, c1, c2, c3, c4};
#pragma unroll
        for (int e = 0; e < 5; e++)
            for (int j = 0; j < 20; j++)
                XA[(e * 20 + j) * PITCH + r] = ((float)j < cnt[e]) ? 1.f : 0.f;
        for (int j = 356; j < 384; j++) XA[j * PITCH + r] = 0.f;  // K padding
    }
    __syncthreads();
    // ---- mean feat into XA rows 100..355 ----
    {
        float* dstc = XA + (100 + g) * PITCH;
#pragma unroll
        for (int i = 0; i < 32; i++) dstc[r0 + i] = accv[i] * invs[r0 + i];
    }
    __syncthreads();

    rownorm(XA + 100 * PITCH, red1, red2, rowM, rowR, tid);               // subset_weighted_norm
    mlp_gemm(XA, XB, cW, cB, W0, W1, 356, 23, 0, tid);                    // combine + relu
    rownorm(XB, red1, red2, rowM, rowR, tid);                             // norm_post_combine
    mlp_gemm(XB, XA, w1, b1, W0, W1, 256, 16, 0, tid);                    // l1 + relu
    mlp_gemm(XA, XB, w2a, b2a, W0, W1, 256, 16, 1, tid);                  // l2a + leaky
    mlp_gemm(XB, XA, w2b, b2b, W0, W1, 256, 16, 0, tid);                  // l2b: leaky+relu == relu
    rownorm(XA, red1, red2, rowM, rowR, tid);                             // norm_pre_score

    // ---- score head ----
    {
        int r = tid & 63, part = tid >> 6;
        float s = 0.f;
#pragma unroll
        for (int gg = 0; gg < 32; gg++)
            s += XA[(part * 32 + gg) * PITCH + r] * sW[part * 32 + gg];
        red1[part * 64 + r] = s;
        __syncthreads();
        if (tid < 64) {
            float t = 0.f;
#pragma unroll
            for (int p = 0; p < 8; p++) t += red1[p * 64 + tid];
            g_scores[b * 4096 + s0 + tid] = t + sB[0];
        }
    }
}

// ---------------- per-batch softmax over 4096 scores ----------------
__global__ void softmax_kernel(float* __restrict__ probs_out) {
    __shared__ float sbuf[32];
    __shared__ float sval;
    int b = blockIdx.x, t = threadIdx.x, lane = t & 31, wid = t >> 5;
    const float* sc = g_scores + b * 4096;
    float v0 = sc[t], v1 = sc[t + 1024], v2 = sc[t + 2048], v3 = sc[t + 3072];
    float mx = fmaxf(fmaxf(v0, v1), fmaxf(v2, v3));
#pragma unroll
    for (int o = 16; o; o >>= 1) mx = fmaxf(mx, __shfl_xor_sync(0xffffffffu, mx, o));
    if (lane == 0) sbuf[wid] = mx;
    __syncthreads();
    if (t < 32) {
        float m = sbuf[t];
#pragma unroll
        for (int o = 16; o; o >>= 1) m = fmaxf(m, __shfl_xor_sync(0xffffffffu, m, o));
        if (t == 0) sval = m;
    }
    __syncthreads();
    mx = sval;
    float e0 = expf(v0 - mx), e1 = expf(v1 - mx), e2 = expf(v2 - mx), e3 = expf(v3 - mx);
    float sum = e0 + e1 + e2 + e3;
#pragma unroll
    for (int o = 16; o; o >>= 1) sum += __shfl_xor_sync(0xffffffffu, sum, o);
    __syncthreads();
    if (lane == 0) sbuf[wid] = sum;
    __syncthreads();
    if (t < 32) {
        float s = sbuf[t];
#pragma unroll
        for (int o = 16; o; o >>= 1) s += __shfl_xor_sync(0xffffffffu, s, o);
        if (t == 0) sval = s;
    }
    __syncthreads();
    float inv = 1.f / sval;
    float p0 = e0 * inv, p1 = e1 * inv, p2 = e2 * inv, p3 = e3 * inv;
    probs_out[b * 4096 + t] = p0;
    probs_out[b * 4096 + t + 1024] = p1;
    probs_out[b * 4096 + t + 2048] = p2;
    probs_out[b * 4096 + t + 3072] = p3;
    g_probs[b * 4096 + t] = p0;
    g_probs[b * 4096 + t + 1024] = p1;
    g_probs[b * 4096 + t + 2048] = p2;
    g_probs[b * 4096 + t + 3072] = p3;
}

// ---------------- zero + scatter into spectral bins ----------------
__global__ void zero_kernel(float* __restrict__ p, int n) {
    int idx = blockIdx.x * blockDim.x + threadIdx.x;
    if (idx < n) p[idx] = 0.f;
}

__global__ void scatter_kernel(const int* __restrict__ midx,
                               const float* __restrict__ inten,
                               float* __restrict__ spect) {
    int idx = blockIdx.x * blockDim.x + threadIdx.x;
    if (idx >= 8 * 4096 * 32) return;
    int b = idx >> 17;              // 4096*32 = 131072
    int s = (idx >> 5) & 4095;
    float w = inten[idx] * g_probs[b * 4096 + s];
    atomicAdd(spect + b * 65536 + midx[idx], w);
}

// ---------------- launch ----------------
extern "C" void kernel_launch(void* const* d_in, const int* in_sizes, int n_in,
                              void* d_out, int out_size) {
    const float* vf    = (const float*)d_in[0];
    const float* vmask = (const float*)d_in[1];
    const float* eoh   = (const float*)d_in[2];
    const int*   subs  = (const int*)d_in[4];
    const int*   midx  = (const int*)d_in[6];
    const float* inten = (const float*)d_in[7];
    const float* cW    = (const float*)d_in[8];
    const float* cB    = (const float*)d_in[9];
    const float* w1    = (const float*)d_in[10];
    const float* b1    = (const float*)d_in[11];
    const float* w2a   = (const float*)d_in[12];
    const float* b2a   = (const float*)d_in[13];
    const float* w2b   = (const float*)d_in[14];
    const float* b2b   = (const float*)d_in[15];
    const float* sW    = (const float*)d_in[16];
    const float* sB    = (const float*)d_in[17];
    float* out = (float*)d_out;

    int pOff = out_size - 8 * 4096;  // spect first, probs second
    size_t smem = (size_t)53216 * sizeof(float);
    cudaFuncSetAttribute(fused_main, cudaFuncAttributeMaxDynamicSharedMemorySize,
                         (int)smem);

    zero_kernel<<<(pOff + 511) / 512, 512>>>(out, pOff);
    fused_main<<<512, TH, smem>>>(vf, vmask, eoh, subs, cW, cB, w1, b1, w2a, b2a,
                                  w2b, b2b, sW, sB);
    softmax_kernel<<<8, 1024>>>(out + pOff);
    scatter_kernel<<<2048, 512>>>(midx, inten, out);
}